// round 14
// baseline (speedup 1.0000x reference)
#include <cuda_runtime.h>
#include <cuda_fp16.h>

#define T 1600
#define BH 64
#define HD 32
// softmax scale * log2(e): scores are computed in exp2 domain
#define QSCALE (0.17677669529663687f * 1.4426950408889634f)

// Pre-fragmented Q/K scratch in fp16 mma fragment order (m16n8k16).
static __device__ unsigned g_Qf[(size_t)BH * 100 * 2 * 32 * 4];
static __device__ unsigned g_Kf[(size_t)BH * 25 * 8 * 32 * 4];
// LN-folded projection weights (fp16) and bias (fp32), built by prep_kernel
static __device__ __half g_Wh[512 * 256];
static __device__ float  g_bq[512];

__device__ __forceinline__ unsigned pack_h2(float a, float b) {
    __half2 h = __floats2half2_rn(a, b);
    return *(unsigned*)&h;
}

// pair exp2 through the f16x2 MUFU path (2 exps per MUFU op)
__device__ __forceinline__ float2 exp2_pair(float a, float b) {
    __half2 h = __floats2half2_rn(a, b);
    unsigned hu = *(unsigned*)&h;
    unsigned r;
    asm("ex2.approx.f16x2 %0, %1;" : "=r"(r) : "r"(hu));
    return __half22float2(*(__half2*)&r);
}

// fp16 mma m16n8k16, fp32 accum
__device__ __forceinline__ void mma_f16(float c[4], const unsigned a[4], const unsigned b[2]) {
    asm volatile(
        "mma.sync.aligned.m16n8k16.row.col.f32.f16.f16.f32 "
        "{%0,%1,%2,%3}, {%4,%5,%6,%7}, {%8,%9}, {%0,%1,%2,%3};\n"
        : "+f"(c[0]), "+f"(c[1]), "+f"(c[2]), "+f"(c[3])
        : "r"(a[0]), "r"(a[1]), "r"(a[2]), "r"(a[3]), "r"(b[0]), "r"(b[1]));
}

__device__ __forceinline__ void cp_async16(unsigned smem_addr, const void* gptr) {
    asm volatile("cp.async.cg.shared.global [%0], [%1], 16;"
                 :: "r"(smem_addr), "l"(gptr));
}

__device__ __forceinline__ void store_qfrag_h2(int bh, int t, int d, unsigned h2) {
    const int rt = t >> 4, gid = t & 7, rhalf = (t >> 3) & 1;
    const int kb = d >> 4, dd = d & 15;
    const int colhalf = dd >> 3, tig = (dd & 7) >> 1;
    g_Qf[(((size_t)bh * 100 + rt) * 2 + kb) * 128 + (gid * 4 + tig) * 4 + colhalf * 2 + rhalf] = h2;
}

__device__ __forceinline__ void store_kfrag_h2(int bh, int t, int d, unsigned h2) {
    const int si = t >> 6, nt = (t >> 3) & 7, gid = t & 7;
    const int kb = d >> 4, dd = d & 15;
    const int bhalf = dd >> 3, tig = (dd & 7) >> 1;
    g_Kf[((((size_t)bh * 25 + si) * 8 + nt) * 32 + gid * 4 + tig) * 4 + kb * 2 + bhalf] = h2;
}

// ===================== Kernel 0: fold LN gamma/beta into W and bias ===============
// 64 blocks x 256 threads: one warp per output row n.
__global__ void __launch_bounds__(256) prep_kernel(
    const float* __restrict__ qkv_w, const float* __restrict__ qkv_b,
    const float* __restrict__ ln_w, const float* __restrict__ ln_b)
{
    const int n = blockIdx.x * 8 + (threadIdx.x >> 5);   // 0..511
    const int lane = threadIdx.x & 31;
    const float* wr = qkv_w + (size_t)n * 256;
    float partial = 0.f;
    #pragma unroll
    for (int j = 0; j < 8; j++) {
        const int c = lane + j * 32;
        const float w = wr[c];
        g_Wh[n * 256 + c] = __float2half(w * ln_w[c]);
        partial += w * ln_b[c];
    }
    #pragma unroll
    for (int o = 16; o; o >>= 1) partial += __shfl_xor_sync(~0u, partial, o);
    if (lane == 0) g_bq[n] = partial + qkv_b[n];
}

// ===================== Kernel 1: LayerNorm + QKV projection (Q,K only) =============
// Token tile pre-normalized ONCE into xn[t][c] fp16 (fp32 math), so each
// a-fragment is 4 conflict-free LDS.32 with zero arithmetic. W' streamed via
// cp.async 2-stage pipeline. LN gamma/beta already folded into W'/b'.
#define XN_HALFS 264           // 256 + 8 pad: a-frag/normalize LDS conflict-free
#define WS_HALFS 72
#define K1_SMEM_BYTES (64 * XN_HALFS * 2 + 2 * 128 * WS_HALFS * 2 + 512)

__global__ void __launch_bounds__(256, 3) ln_qkv_kernel(const float* __restrict__ feat)
{
    extern __shared__ char sm1[];
    __half* xn = (__half*)sm1;                                      // [64][264]
    __half* wsh = (__half*)(sm1 + 64 * XN_HALFS * 2);               // [2][128][72]
    float*  mus = (float*)(sm1 + 64 * XN_HALFS * 2 + 2 * 128 * WS_HALFS * 2);
    float*  rss = mus + 64;

    const int tid = threadIdx.x;
    const int n0 = blockIdx.x * 128;        // 0,128 -> Q ; 256,384 -> K
    const int tb = blockIdx.y;              // 0..199
    const int b  = tb / 25;
    const int t0 = (tb % 25) * 64;

    const unsigned ws_u32 = (unsigned)__cvta_generic_to_shared(wsh);

    // prefetch W' chunk kc into stage s: 128 rows x 128B, row stride 144B
    #define PREW(kc, s) {                                                       \
        _Pragma("unroll")                                                       \
        for (int j = 0; j < 4; j++) {                                           \
            const int ch = tid + j * 256;                                       \
            const int r = ch >> 3, cj = ch & 7;                                 \
            cp_async16(ws_u32 + (s) * (128 * WS_HALFS * 2) + r * (WS_HALFS * 2) \
                       + cj * 16,                                               \
                       (const char*)(g_Wh + (size_t)(n0 + r) * 256 + (kc) * 64) \
                       + cj * 16);                                              \
        }                                                                       \
        asm volatile("cp.async.commit_group;"); }

    PREW(0, 0)

    // Load x tile feat[b][c][t0..t0+63] -> xn[t][c] fp16 (transposed store)
    {
        const float* src = feat + ((size_t)b * 256) * T + t0;
        const int t4 = (tid & 15) * 4;
        #pragma unroll 4
        for (int c = tid >> 4; c < 256; c += 16) {
            const float4 v = *(const float4*)(src + (size_t)c * T + t4);
            xn[(t4 + 0) * XN_HALFS + c] = __float2half(v.x);
            xn[(t4 + 1) * XN_HALFS + c] = __float2half(v.y);
            xn[(t4 + 2) * XN_HALFS + c] = __float2half(v.z);
            xn[(t4 + 3) * XN_HALFS + c] = __float2half(v.w);
        }
    }
    __syncthreads();

    // LN stats: 4 threads per token, strided over c
    const int tok = tid >> 2, g4 = tid & 3;
    {
        float s = 0.f, sq = 0.f;
        for (int c = g4; c < 256; c += 4) {
            const float v = __half2float(xn[tok * XN_HALFS + c]);
            s += v; sq += v * v;
        }
        s += __shfl_xor_sync(~0u, s, 1); sq += __shfl_xor_sync(~0u, sq, 1);
        s += __shfl_xor_sync(~0u, s, 2); sq += __shfl_xor_sync(~0u, sq, 2);
        if (g4 == 0) {
            const float mu = s * (1.f / 256.f);
            mus[tok] = mu;
            rss[tok] = rsqrtf(sq * (1.f / 256.f) - mu * mu + 1e-6f);
        }
    }
    __syncthreads();

    // Normalize in place (fp32 math), conflict-free half2 interleave:
    // thread g4 handles half2 cols {g4*2 + 8j}
    {
        const float mu = mus[tok], rs = rss[tok];
        __half2* row = (__half2*)(xn + tok * XN_HALFS);
        #pragma unroll
        for (int j = 0; j < 32; j++) {
            const int w = g4 + 4 * j;
            float2 f = __half22float2(row[w]);
            row[w] = __floats2half2_rn((f.x - mu) * rs, (f.y - mu) * rs);
        }
    }
    __syncthreads();

    const int warp = tid >> 5, lane = tid & 31;
    const int wm = warp >> 1, wn = warp & 1;
    const int gid = lane >> 2, tig = lane & 3;
    const int tl = wm * 16 + gid;

    float acc[8][4];
    #pragma unroll
    for (int i = 0; i < 8; i++) {
        #pragma unroll
        for (int j = 0; j < 4; j++) acc[i][j] = 0.f;
    }

    const unsigned* ws32 = (const unsigned*)wsh;
    const unsigned* xrow0 = (const unsigned*)(xn + tl * XN_HALFS);
    const unsigned* xrow1 = (const unsigned*)(xn + (tl + 8) * XN_HALFS);

    for (int kc = 0; kc < 4; kc++) {
        if (kc + 1 < 4) PREW(kc + 1, (kc + 1) & 1)
        if (kc + 1 < 4) { asm volatile("cp.async.wait_group 1;"); }
        else            { asm volatile("cp.async.wait_group 0;"); }
        __syncthreads();
        const unsigned* wstage = ws32 + (kc & 1) * (128 * WS_HALFS / 2);
        #pragma unroll
        for (int kk = 0; kk < 4; kk++) {       // 4 k16-blocks per 64-chunk
            const int w0 = (kc * 64 + kk * 16) / 2 + tig;   // word index of cols cb,cb+1
            unsigned a[4];
            a[0] = xrow0[w0];
            a[1] = xrow1[w0];
            a[2] = xrow0[w0 + 4];
            a[3] = xrow1[w0 + 4];
            #pragma unroll
            for (int nt = 0; nt < 8; nt++) {
                const int nl = wn * 64 + nt * 8 + gid;
                unsigned bf[2];
                bf[0] = wstage[nl * (WS_HALFS / 2) + kk * 8 + tig];
                bf[1] = wstage[nl * (WS_HALFS / 2) + kk * 8 + 4 + tig];
                mma_f16(acc[nt], a, bf);
            }
        }
        __syncthreads();
    }

    // Epilogue: folded bias, fold (scale*log2e) into Q, pack fp16 fragment pairs
    const bool is_q = (n0 < 256);
    const int trow = t0 + tl;
    #pragma unroll
    for (int nt = 0; nt < 8; nt++) {
        const int ng = n0 + wn * 64 + nt * 8 + 2 * tig;
        const int nq = is_q ? ng : (ng - 256);
        const int h = nq >> 5, d = nq & 31;
        const int bh = b * 8 + h;
        const float bias0 = g_bq[ng], bias1 = g_bq[ng + 1];
        float v0 = acc[nt][0] + bias0, v1 = acc[nt][1] + bias1;
        float v2 = acc[nt][2] + bias0, v3 = acc[nt][3] + bias1;
        if (is_q) {
            v0 *= QSCALE; v1 *= QSCALE; v2 *= QSCALE; v3 *= QSCALE;
            store_qfrag_h2(bh, trow,     d, pack_h2(v0, v1));
            store_qfrag_h2(bh, trow + 8, d, pack_h2(v2, v3));
        } else {
            store_kfrag_h2(bh, trow,     d, pack_h2(v0, v1));
            store_kfrag_h2(bh, trow + 8, d, pack_h2(v2, v3));
        }
    }
    #undef PREW
}

// ===================== Kernel 2: fp16 mma + cp.async 4-stage pipeline ============
// Unchanged from r13 (proven): 2x2 warp split, 4x4KB stages depth 3, f16x2 exp
// in both passes.
#define NSTAGE 4

__global__ void __launch_bounds__(128, 7) attn_kernel(float* __restrict__ out)
{
    __shared__ uint4 Ks[NSTAGE][256];      // 4 x 4KB chunk stages
    __shared__ float red[2][64];

    const int tid = threadIdx.x;
    const int warp = tid >> 5, lane = tid & 31;
    const int gid = lane >> 2, tig = lane & 3;
    const int wm = warp >> 1, wn = warp & 1;
    const int bh = blockIdx.y;
    const int t0 = blockIdx.x * 64;

    unsigned afr[2][2][4];
    #pragma unroll
    for (int mf = 0; mf < 2; mf++) {
        const int rt = blockIdx.x * 4 + wm * 2 + mf;
        const uint4* qf = (const uint4*)g_Qf + ((size_t)bh * 100 + rt) * 2 * 32 + lane;
        #pragma unroll
        for (int kb = 0; kb < 2; kb++) {
            const uint4 v = qf[kb * 32];
            afr[mf][kb][0] = v.x; afr[mf][kb][1] = v.y;
            afr[mf][kb][2] = v.z; afr[mf][kb][3] = v.w;
        }
    }

    const uint4* ksrc = (const uint4*)g_Kf + (size_t)bh * 25 * 256;
    const unsigned ks_u32 = (unsigned)__cvta_generic_to_shared(&Ks[0][0]) + tid * 16;

    #define PREFETCH(c, s) {                                                  \
        const unsigned d_ = ks_u32 + (s) * 4096;                              \
        const uint4* s_ = ksrc + (size_t)(c) * 256 + tid;                     \
        cp_async16(d_,        s_);                                            \
        cp_async16(d_ + 2048, s_ + 128);                                      \
        asm volatile("cp.async.commit_group;"); }

    #define MMA_GROUP(kf)                                                     \
        const unsigned b0[2] = {(kf).x, (kf).y};                              \
        const unsigned b1[2] = {(kf).z, (kf).w};                              \
        float c0[4] = {0.f,0.f,0.f,0.f}, c1[4] = {0.f,0.f,0.f,0.f};           \
        mma_f16(c0, afr[0][0], b0); mma_f16(c1, afr[1][0], b0);               \
        mma_f16(c0, afr[0][1], b1); mma_f16(c1, afr[1][1], b1);

    float sums[4] = {0.f, 0.f, 0.f, 0.f};
    float inv[4];
    float* const obase = out + ((size_t)bh * T + t0 + wm * 32 + gid) * T + 2 * tig;

    PREFETCH(0, 0)
    PREFETCH(1, 1)
    PREFETCH(2, 2)

    for (int gi = 0; gi < 50; gi++) {
        asm volatile("cp.async.wait_group 2;");
        __syncthreads();
        {
            const int c3 = gi + 3;
            const int ch = (c3 >= 50) ? (c3 - 50) : (c3 >= 25 ? c3 - 25 : c3);
            PREFETCH(ch, c3 & 3)
        }
        const uint4* kb4 = Ks[gi & 3];
        if (gi < 25) {
            #pragma unroll
            for (int g = 0; g < 4; g++) {
                const int ntg = wn * 4 + g;
                const uint4 kf = kb4[ntg * 32 + lane];
                MMA_GROUP(kf)
                const float2 e0 = exp2_pair(c0[0], c0[1]);
                const float2 e1 = exp2_pair(c0[2], c0[3]);
                const float2 e2 = exp2_pair(c1[0], c1[1]);
                const float2 e3 = exp2_pair(c1[2], c1[3]);
                sums[0] += e0.x + e0.y;
                sums[1] += e1.x + e1.y;
                sums[2] += e2.x + e2.y;
                sums[3] += e3.x + e3.y;
            }
            if (gi == 24) {
                #pragma unroll
                for (int i = 0; i < 4; i++) {
                    sums[i] += __shfl_xor_sync(~0u, sums[i], 1);
                    sums[i] += __shfl_xor_sync(~0u, sums[i], 2);
                }
                if (tig == 0) {
                    #pragma unroll
                    for (int mf = 0; mf < 2; mf++) {
                        red[wn][wm * 32 + mf * 16 + gid]     = sums[mf * 2];
                        red[wn][wm * 32 + mf * 16 + 8 + gid] = sums[mf * 2 + 1];
                    }
                }
                __syncthreads();
                #pragma unroll
                for (int mf = 0; mf < 2; mf++) {
                    const int lr0 = wm * 32 + mf * 16 + gid;
                    inv[mf * 2]     = 1.0f / (red[0][lr0] + red[1][lr0]);
                    inv[mf * 2 + 1] = 1.0f / (red[0][lr0 + 8] + red[1][lr0 + 8]);
                }
            }
        } else {
            const int ci = gi - 25;
            #pragma unroll
            for (int g = 0; g < 4; g++) {
                const int ntg = wn * 4 + g;
                const uint4 kf = kb4[ntg * 32 + lane];
                MMA_GROUP(kf)
                const float2 e0 = exp2_pair(c0[0], c0[1]);
                const float2 e1 = exp2_pair(c0[2], c0[3]);
                const float2 e2 = exp2_pair(c1[0], c1[1]);
                const float2 e3 = exp2_pair(c1[2], c1[3]);
                float* pp = obase + ci * 64 + ntg * 8;
                *(float2*)pp            = make_float2(e0.x * inv[0], e0.y * inv[0]);
                *(float2*)(pp + 8 * T)  = make_float2(e1.x * inv[1], e1.y * inv[1]);
                *(float2*)(pp + 16 * T) = make_float2(e2.x * inv[2], e2.y * inv[2]);
                *(float2*)(pp + 24 * T) = make_float2(e3.x * inv[3], e3.y * inv[3]);
            }
        }
    }

    #undef PREFETCH
    #undef MMA_GROUP
}

extern "C" void kernel_launch(void* const* d_in, const int* in_sizes, int n_in,
                              void* d_out, int out_size)
{
    (void)in_sizes; (void)n_in; (void)out_size;
    const float* feat  = (const float*)d_in[0];
    const float* ln_w  = (const float*)d_in[1];
    const float* ln_b  = (const float*)d_in[2];
    const float* qkv_w = (const float*)d_in[3];
    const float* qkv_b = (const float*)d_in[4];
    float* out = (float*)d_out;

    cudaFuncSetAttribute(ln_qkv_kernel, cudaFuncAttributeMaxDynamicSharedMemorySize,
                         K1_SMEM_BYTES);

    prep_kernel<<<64, 256>>>(qkv_w, qkv_b, ln_w, ln_b);
    ln_qkv_kernel<<<dim3(4, 200), 256, K1_SMEM_BYTES>>>(feat);
    attn_kernel<<<dim3(25, 64), 128>>>(out);
}

// round 16
// speedup vs baseline: 1.0269x; 1.0269x over previous
#include <cuda_runtime.h>
#include <cuda_fp16.h>

#define T 1600
#define BH 64
#define HD 32
// softmax scale * log2(e): scores are computed in exp2 domain
#define QSCALE (0.17677669529663687f * 1.4426950408889634f)

// Pre-fragmented Q/K scratch in fp16 mma fragment order (m16n8k16).
static __device__ unsigned g_Qf[(size_t)BH * 100 * 2 * 32 * 4];
static __device__ unsigned g_Kf[(size_t)BH * 25 * 8 * 32 * 4];
// LN-folded projection weights (fp16) and bias (fp32), built by prep_kernel
static __device__ __half g_Wh[512 * 256];
static __device__ float  g_bq[512];

__device__ __forceinline__ unsigned pack_h2(float a, float b) {
    __half2 h = __floats2half2_rn(a, b);
    return *(unsigned*)&h;
}

// pair exp2 through the f16x2 MUFU path (2 exps per MUFU op)
__device__ __forceinline__ float2 exp2_pair(float a, float b) {
    __half2 h = __floats2half2_rn(a, b);
    unsigned hu = *(unsigned*)&h;
    unsigned r;
    asm("ex2.approx.f16x2 %0, %1;" : "=r"(r) : "r"(hu));
    return __half22float2(*(__half2*)&r);
}

// fp16 mma m16n8k16, fp32 accum
__device__ __forceinline__ void mma_f16(float c[4], const unsigned a[4], const unsigned b[2]) {
    asm volatile(
        "mma.sync.aligned.m16n8k16.row.col.f32.f16.f16.f32 "
        "{%0,%1,%2,%3}, {%4,%5,%6,%7}, {%8,%9}, {%0,%1,%2,%3};\n"
        : "+f"(c[0]), "+f"(c[1]), "+f"(c[2]), "+f"(c[3])
        : "r"(a[0]), "r"(a[1]), "r"(a[2]), "r"(a[3]), "r"(b[0]), "r"(b[1]));
}

__device__ __forceinline__ void cp_async16(unsigned smem_addr, const void* gptr) {
    asm volatile("cp.async.cg.shared.global [%0], [%1], 16;"
                 :: "r"(smem_addr), "l"(gptr));
}

// paired Q store: rows t (rhalf=0) and t+8 (rhalf=1) of col pair d are adjacent
// words in g_Qf -> one 8B store
__device__ __forceinline__ void store_qfrag_h2x2(int bh, int t, int d, unsigned lo, unsigned hi) {
    const int rt = t >> 4, gid = t & 7;
    const int kb = d >> 4, dd = d & 15;
    const int colhalf = dd >> 3, tig = (dd & 7) >> 1;
    uint2* p = (uint2*)&g_Qf[(((size_t)bh * 100 + rt) * 2 + kb) * 128
                             + (gid * 4 + tig) * 4 + colhalf * 2];
    *p = make_uint2(lo, hi);
}

__device__ __forceinline__ void store_kfrag_h2(int bh, int t, int d, unsigned h2) {
    const int si = t >> 6, nt = (t >> 3) & 7, gid = t & 7;
    const int kb = d >> 4, dd = d & 15;
    const int bhalf = dd >> 3, tig = (dd & 7) >> 1;
    g_Kf[((((size_t)bh * 25 + si) * 8 + nt) * 32 + gid * 4 + tig) * 4 + kb * 2 + bhalf] = h2;
}

// ===================== Kernel 0: fold LN gamma/beta into W and bias ===============
// W'[n][c] = W[n][c]*lnw[c] (fp16);  b'[n] = sum_c W[n][c]*lnb[c] + b[n]
__global__ void __launch_bounds__(32) prep_kernel(
    const float* __restrict__ qkv_w, const float* __restrict__ qkv_b,
    const float* __restrict__ ln_w, const float* __restrict__ ln_b)
{
    const int n = blockIdx.x;           // 0..511
    const int lane = threadIdx.x;
    const float* wr = qkv_w + (size_t)n * 256;
    float partial = 0.f;
    #pragma unroll
    for (int j = 0; j < 8; j++) {
        const int c = lane + j * 32;
        const float w = wr[c];
        g_Wh[n * 256 + c] = __float2half(w * ln_w[c]);
        partial += w * ln_b[c];
    }
    #pragma unroll
    for (int o = 16; o; o >>= 1) partial += __shfl_xor_sync(~0u, partial, o);
    if (lane == 0) g_bq[n] = partial + qkv_b[n];
}

// ===================== Kernel 1: LayerNorm + QKV projection (Q,K only) =============
// r13 structure (proven): fp16 end-to-end; W' streamed via cp.async 2-stage
// pipeline; LN applied per a-frag element (folded gamma/beta in W'/b').
#define XS_HALFS 72            // halves per c-row (conflict-free a-frag loads)
#define WS_HALFS 72            // halves per n-row per stage (conflict-free b-frags)
#define K1_SMEM_BYTES (256 * XS_HALFS * 2 + 2 * 128 * WS_HALFS * 2 + 512)

__global__ void __launch_bounds__(256, 3) ln_qkv_kernel(const float* __restrict__ feat)
{
    extern __shared__ char sm1[];
    __half* xs = (__half*)sm1;                                      // [256][72]
    __half* wsh = (__half*)(sm1 + 256 * XS_HALFS * 2);              // [2][128][72]
    float*  mus = (float*)(sm1 + 256 * XS_HALFS * 2 + 2 * 128 * WS_HALFS * 2);
    float*  rss = mus + 64;

    const int tid = threadIdx.x;
    const int n0 = blockIdx.x * 128;        // 0,128 -> Q ; 256,384 -> K
    const int tb = blockIdx.y;              // 0..199
    const int b  = tb / 25;
    const int t0 = (tb % 25) * 64;

    const unsigned ws_u32 = (unsigned)__cvta_generic_to_shared(wsh);

    // prefetch W' chunk kc into stage s: 128 rows x 128B, row stride 144B
    #define PREW(kc, s) {                                                       \
        _Pragma("unroll")                                                       \
        for (int j = 0; j < 4; j++) {                                           \
            const int ch = tid + j * 256;                                       \
            const int r = ch >> 3, cj = ch & 7;                                 \
            cp_async16(ws_u32 + (s) * (128 * WS_HALFS * 2) + r * (WS_HALFS * 2) \
                       + cj * 16,                                               \
                       (const char*)(g_Wh + (size_t)(n0 + r) * 256 + (kc) * 64) \
                       + cj * 16);                                              \
        }                                                                       \
        asm volatile("cp.async.commit_group;"); }

    PREW(0, 0)

    // Load x tile (feat[b][c][t0..t0+63]) into fp16 smem, coalesced float4
    {
        const float* src = feat + ((size_t)b * 256) * T + t0;
        const int c4 = (tid & 15) * 4;
        #pragma unroll 4
        for (int c = tid >> 4; c < 256; c += 16) {
            const float4 v = *(const float4*)(src + (size_t)c * T + c4);
            __half2* d = (__half2*)(xs + c * XS_HALFS + c4);
            d[0] = __floats2half2_rn(v.x, v.y);
            d[1] = __floats2half2_rn(v.z, v.w);
        }
    }
    __syncthreads();

    // LN stats: 4 threads per token
    {
        const int t = tid >> 2, g = tid & 3;
        float s = 0.f, sq = 0.f;
        for (int c = g; c < 256; c += 4) {
            const float v = __half2float(xs[c * XS_HALFS + t]);
            s += v; sq += v * v;
        }
        s += __shfl_xor_sync(~0u, s, 1); sq += __shfl_xor_sync(~0u, sq, 1);
        s += __shfl_xor_sync(~0u, s, 2); sq += __shfl_xor_sync(~0u, sq, 2);
        if (g == 0) {
            const float mu = s * (1.f / 256.f);
            mus[t] = mu;
            rss[t] = rsqrtf(sq * (1.f / 256.f) - mu * mu + 1e-6f);
        }
    }
    __syncthreads();

    const int warp = tid >> 5, lane = tid & 31;
    const int wm = warp >> 1, wn = warp & 1;
    const int gid = lane >> 2, tig = lane & 3;
    const int tl = wm * 16 + gid;
    const float rs0 = rss[tl], mrs0 = mus[tl] * rs0;
    const float rs1 = rss[tl + 8], mrs1 = mus[tl + 8] * rs1;

    float acc[8][4];
    #pragma unroll
    for (int i = 0; i < 8; i++) {
        #pragma unroll
        for (int j = 0; j < 4; j++) acc[i][j] = 0.f;
    }

    const unsigned* ws32 = (const unsigned*)wsh;

    for (int kc = 0; kc < 4; kc++) {
        if (kc + 1 < 4) PREW(kc + 1, (kc + 1) & 1)
        if (kc + 1 < 4) { asm volatile("cp.async.wait_group 1;"); }
        else            { asm volatile("cp.async.wait_group 0;"); }
        __syncthreads();
        const unsigned* wstage = ws32 + (kc & 1) * (128 * WS_HALFS / 2);
        #pragma unroll
        for (int kk = 0; kk < 4; kk++) {       // 4 k16-blocks per 64-chunk
            const int cb = kc * 64 + kk * 16 + 2 * tig;
            float va0[4], va1[4];              // rows tl/tl+8; cols cb,cb+1,cb+8,cb+9
            #pragma unroll
            for (int j = 0; j < 4; j++) {
                const int c = cb + (j >> 1) * 8 + (j & 1);
                const float x0 = __half2float(xs[c * XS_HALFS + tl]);
                const float x1 = __half2float(xs[c * XS_HALFS + tl + 8]);
                va0[j] = fmaf(x0, rs0, -mrs0);
                va1[j] = fmaf(x1, rs1, -mrs1);
            }
            unsigned a[4];
            a[0] = pack_h2(va0[0], va0[1]);
            a[1] = pack_h2(va1[0], va1[1]);
            a[2] = pack_h2(va0[2], va0[3]);
            a[3] = pack_h2(va1[2], va1[3]);
            #pragma unroll
            for (int nt = 0; nt < 8; nt++) {
                const int nl = wn * 64 + nt * 8 + gid;
                unsigned bf[2];
                bf[0] = wstage[nl * (WS_HALFS / 2) + kk * 8 + tig];
                bf[1] = wstage[nl * (WS_HALFS / 2) + kk * 8 + 4 + tig];
                mma_f16(acc[nt], a, bf);
            }
        }
        __syncthreads();
    }

    // Epilogue: folded bias, fold (scale*log2e) into Q, pack fp16 fragment pairs.
    // Q row-pair (trow, trow+8) stores combine into one STG.64.
    const bool is_q = (n0 < 256);
    const int trow = t0 + tl;
    #pragma unroll
    for (int nt = 0; nt < 8; nt++) {
        const int ng = n0 + wn * 64 + nt * 8 + 2 * tig;
        const int nq = is_q ? ng : (ng - 256);
        const int h = nq >> 5, d = nq & 31;
        const int bh = b * 8 + h;
        const float bias0 = g_bq[ng], bias1 = g_bq[ng + 1];
        float v0 = acc[nt][0] + bias0, v1 = acc[nt][1] + bias1;
        float v2 = acc[nt][2] + bias0, v3 = acc[nt][3] + bias1;
        if (is_q) {
            v0 *= QSCALE; v1 *= QSCALE; v2 *= QSCALE; v3 *= QSCALE;
            store_qfrag_h2x2(bh, trow, d, pack_h2(v0, v1), pack_h2(v2, v3));
        } else {
            store_kfrag_h2(bh, trow,     d, pack_h2(v0, v1));
            store_kfrag_h2(bh, trow + 8, d, pack_h2(v2, v3));
        }
    }
    #undef PREW
}

// ===================== Kernel 2: fp16 mma + cp.async 6-stage pipeline ============
// r13 structure with pipeline depth 3 -> 5 (6 x 4KB stages, wait_group 4):
// deeper cover absorbs L2/DRAM latency spikes at wave transitions.
#define NSTAGE 6

__global__ void __launch_bounds__(128, 7) attn_kernel(float* __restrict__ out)
{
    __shared__ uint4 Ks[NSTAGE][256];      // 6 x 4KB chunk stages
    __shared__ float red[2][64];

    const int tid = threadIdx.x;
    const int warp = tid >> 5, lane = tid & 31;
    const int gid = lane >> 2, tig = lane & 3;
    const int wm = warp >> 1, wn = warp & 1;
    const int bh = blockIdx.y;
    const int t0 = blockIdx.x * 64;

    unsigned afr[2][2][4];
    #pragma unroll
    for (int mf = 0; mf < 2; mf++) {
        const int rt = blockIdx.x * 4 + wm * 2 + mf;
        const uint4* qf = (const uint4*)g_Qf + ((size_t)bh * 100 + rt) * 2 * 32 + lane;
        #pragma unroll
        for (int kb = 0; kb < 2; kb++) {
            const uint4 v = qf[kb * 32];
            afr[mf][kb][0] = v.x; afr[mf][kb][1] = v.y;
            afr[mf][kb][2] = v.z; afr[mf][kb][3] = v.w;
        }
    }

    const uint4* ksrc = (const uint4*)g_Kf + (size_t)bh * 25 * 256;
    const unsigned ks_u32 = (unsigned)__cvta_generic_to_shared(&Ks[0][0]) + tid * 16;

    #define PREFETCH(c, s) {                                                  \
        const unsigned d_ = ks_u32 + (s) * 4096;                              \
        const uint4* s_ = ksrc + (size_t)(c) * 256 + tid;                     \
        cp_async16(d_,        s_);                                            \
        cp_async16(d_ + 2048, s_ + 128);                                      \
        asm volatile("cp.async.commit_group;"); }

    #define MMA_GROUP(kf)                                                     \
        const unsigned b0[2] = {(kf).x, (kf).y};                              \
        const unsigned b1[2] = {(kf).z, (kf).w};                              \
        float c0[4] = {0.f,0.f,0.f,0.f}, c1[4] = {0.f,0.f,0.f,0.f};           \
        mma_f16(c0, afr[0][0], b0); mma_f16(c1, afr[1][0], b0);               \
        mma_f16(c0, afr[0][1], b1); mma_f16(c1, afr[1][1], b1);

    float sums[4] = {0.f, 0.f, 0.f, 0.f};
    float inv[4];
    float* const obase = out + ((size_t)bh * T + t0 + wm * 32 + gid) * T + 2 * tig;

    // prime 5 stages (chunks 0..4)
    PREFETCH(0, 0)
    PREFETCH(1, 1)
    PREFETCH(2, 2)
    PREFETCH(3, 3)
    PREFETCH(4, 4)

    int sc = 0;       // consume stage
    int ps = 5;       // prefetch stage = (gi + 5) % 6

    for (int gi = 0; gi < 50; gi++) {
        asm volatile("cp.async.wait_group 4;");
        __syncthreads();   // chunk gi ready; stage ps (consumed at gi-1) reusable
        {   // prefetch chunk gi+5 (wraps; tail wraps are harmless reloads)
            const int c5 = gi + 5;
            const int ch = (c5 >= 50) ? (c5 - 50) : (c5 >= 25 ? c5 - 25 : c5);
            PREFETCH(ch, ps)
        }
        const uint4* kb4 = Ks[sc];
        if (gi < 25) {
            #pragma unroll
            for (int g = 0; g < 4; g++) {
                const int ntg = wn * 4 + g;
                const uint4 kf = kb4[ntg * 32 + lane];
                MMA_GROUP(kf)
                const float2 e0 = exp2_pair(c0[0], c0[1]);
                const float2 e1 = exp2_pair(c0[2], c0[3]);
                const float2 e2 = exp2_pair(c1[0], c1[1]);
                const float2 e3 = exp2_pair(c1[2], c1[3]);
                sums[0] += e0.x + e0.y;
                sums[1] += e1.x + e1.y;
                sums[2] += e2.x + e2.y;
                sums[3] += e3.x + e3.y;
            }
            if (gi == 24) {
                #pragma unroll
                for (int i = 0; i < 4; i++) {
                    sums[i] += __shfl_xor_sync(~0u, sums[i], 1);
                    sums[i] += __shfl_xor_sync(~0u, sums[i], 2);
                }
                if (tig == 0) {
                    #pragma unroll
                    for (int mf = 0; mf < 2; mf++) {
                        red[wn][wm * 32 + mf * 16 + gid]     = sums[mf * 2];
                        red[wn][wm * 32 + mf * 16 + 8 + gid] = sums[mf * 2 + 1];
                    }
                }
                __syncthreads();
                #pragma unroll
                for (int mf = 0; mf < 2; mf++) {
                    const int lr0 = wm * 32 + mf * 16 + gid;
                    inv[mf * 2]     = 1.0f / (red[0][lr0] + red[1][lr0]);
                    inv[mf * 2 + 1] = 1.0f / (red[0][lr0 + 8] + red[1][lr0 + 8]);
                }
            }
        } else {
            const int ci = gi - 25;
            #pragma unroll
            for (int g = 0; g < 4; g++) {
                const int ntg = wn * 4 + g;
                const uint4 kf = kb4[ntg * 32 + lane];
                MMA_GROUP(kf)
                const float2 e0 = exp2_pair(c0[0], c0[1]);
                const float2 e1 = exp2_pair(c0[2], c0[3]);
                const float2 e2 = exp2_pair(c1[0], c1[1]);
                const float2 e3 = exp2_pair(c1[2], c1[3]);
                float* pp = obase + ci * 64 + ntg * 8;
                *(float2*)pp            = make_float2(e0.x * inv[0], e0.y * inv[0]);
                *(float2*)(pp + 8 * T)  = make_float2(e1.x * inv[1], e1.y * inv[1]);
                *(float2*)(pp + 16 * T) = make_float2(e2.x * inv[2], e2.y * inv[2]);
                *(float2*)(pp + 24 * T) = make_float2(e3.x * inv[3], e3.y * inv[3]);
            }
        }
        if (++sc == NSTAGE) sc = 0;
        if (++ps == NSTAGE) ps = 0;
    }

    #undef PREFETCH
    #undef MMA_GROUP
}

extern "C" void kernel_launch(void* const* d_in, const int* in_sizes, int n_in,
                              void* d_out, int out_size)
{
    (void)in_sizes; (void)n_in; (void)out_size;
    const float* feat  = (const float*)d_in[0];
    const float* ln_w  = (const float*)d_in[1];
    const float* ln_b  = (const float*)d_in[2];
    const float* qkv_w = (const float*)d_in[3];
    const float* qkv_b = (const float*)d_in[4];
    float* out = (float*)d_out;

    cudaFuncSetAttribute(ln_qkv_kernel, cudaFuncAttributeMaxDynamicSharedMemorySize,
                         K1_SMEM_BYTES);

    prep_kernel<<<512, 32>>>(qkv_w, qkv_b, ln_w, ln_b);
    ln_qkv_kernel<<<dim3(4, 200), 256, K1_SMEM_BYTES>>>(feat);
    attn_kernel<<<dim3(25, 64), 128>>>(out);
}